// round 13
// baseline (speedup 1.0000x reference)
#include <cuda_runtime.h>
#include <cuda_fp16.h>
#include <float.h>
#include <math.h>

#define H 4096
#define V 32000
#define G (4 * H)
#define STEPS 20

#define GATES_BLOCK 256
#define GATES_GRID  (G / 8)     // 2048 blocks, 8 rows (warps) each
#define LOGIT_BLOCK 256
#define LOGIT_GRID  (V / 8)     // 4000 blocks

// Sequential decode state in device globals (no allocation allowed).
__device__ float g_h[H];
__device__ float g_c[H];
__device__ float g_gates[G];
__device__ int   g_tok;
__device__ unsigned g_ctr_gates;   // zero-init at load; tail block resets to 0
__device__ unsigned g_ctr_logits;

// fp16 weight cache (static device scratch: 128 + 128 + 250 MB).
__device__ __half g_Wih[(size_t)G * H];
__device__ __half g_Whh[(size_t)G * H];
__device__ __half g_Wout[(size_t)V * H];

// ---------------------------------------------------------------------------
// fp32 -> fp16 conversion: 8 floats (2x float4) -> 1 uint4 per thread.
// ---------------------------------------------------------------------------
__device__ __forceinline__ uint4 f8_to_h8(float4 a, float4 b) {
    __half2 h0 = __floats2half2_rn(a.x, a.y);
    __half2 h1 = __floats2half2_rn(a.z, a.w);
    __half2 h2 = __floats2half2_rn(b.x, b.y);
    __half2 h3 = __floats2half2_rn(b.z, b.w);
    uint4 o;
    o.x = *reinterpret_cast<unsigned*>(&h0);
    o.y = *reinterpret_cast<unsigned*>(&h1);
    o.z = *reinterpret_cast<unsigned*>(&h2);
    o.w = *reinterpret_cast<unsigned*>(&h3);
    return o;
}

__global__ void convert_wih(const float4* __restrict__ src) {
    int i = blockIdx.x * blockDim.x + threadIdx.x;   // G*H/8 threads
    ((uint4*)g_Wih)[i] = f8_to_h8(src[2 * i], src[2 * i + 1]);
}
__global__ void convert_whh(const float4* __restrict__ src) {
    int i = blockIdx.x * blockDim.x + threadIdx.x;
    ((uint4*)g_Whh)[i] = f8_to_h8(src[2 * i], src[2 * i + 1]);
}
__global__ void convert_wout(const float4* __restrict__ src) {
    int i = blockIdx.x * blockDim.x + threadIdx.x;   // V*H/8 threads
    ((uint4*)g_Wout)[i] = f8_to_h8(src[2 * i], src[2 * i + 1]);
}

// ---------------------------------------------------------------------------
// init: h0 = noise + image_features, c0 = 0, tok0 = START_TOKEN (0)
// ---------------------------------------------------------------------------
__global__ void init_kernel(const float* __restrict__ imgf,
                            const float* __restrict__ noise) {
    int i = blockIdx.x * blockDim.x + threadIdx.x;
    if (i < H) {
        g_h[i] = imgf[i] + noise[i];
        g_c[i] = 0.0f;
    }
    if (i == 0) { g_tok = 0; g_ctr_gates = 0; g_ctr_logits = 0; }
}

// 8 fp16 weights (one uint4) dotted with 8 fp32 activations, fp32 accumulate.
__device__ __forceinline__ float dot8(uint4 a, float4 v0, float4 v1) {
    const __half2* p = reinterpret_cast<const __half2*>(&a);
    float2 f0 = __half22float2(p[0]);
    float2 f1 = __half22float2(p[1]);
    float2 f2 = __half22float2(p[2]);
    float2 f3 = __half22float2(p[3]);
    return f0.x * v0.x + f0.y * v0.y + f1.x * v0.z + f1.y * v0.w
         + f2.x * v1.x + f2.y * v1.y + f3.x * v1.z + f3.y * v1.w;
}

__device__ __forceinline__ float warp_reduce_sum(float v) {
    #pragma unroll
    for (int o = 16; o > 0; o >>= 1)
        v += __shfl_down_sync(0xffffffffu, v, o);
    return v;
}

__device__ __forceinline__ float sigmoidf_(float x) {
    return 1.0f / (1.0f + expf(-x));
}

// ---------------------------------------------------------------------------
// gates: one warp per row (8 rows per 256-thread block). The last-finishing
// block additionally performs the LSTM cell update (fused, saves a launch).
// ---------------------------------------------------------------------------
__global__ void __launch_bounds__(GATES_BLOCK)
gates_kernel(const float* __restrict__ emb,
             const float* __restrict__ bih,
             const float* __restrict__ bhh) {
    int w    = threadIdx.x >> 5;
    int lane = threadIdx.x & 31;
    int row  = blockIdx.x * 8 + w;

    const float4* x  = (const float4*)(emb + (size_t)g_tok * H);
    const float4* hh = (const float4*)g_h;
    const uint4*  wi = (const uint4*)(g_Wih + (size_t)row * H);
    const uint4*  wh = (const uint4*)(g_Whh + (size_t)row * H);

    float acc = 0.0f;
    #pragma unroll 4
    for (int i = 0; i < H / 8 / 32; i++) {   // 16 iterations per lane
        int c = lane + i * 32;
        uint4  a  = wi[c];
        uint4  b  = wh[c];
        float4 x0 = x[2 * c], x1 = x[2 * c + 1];
        float4 h0 = hh[2 * c], h1 = hh[2 * c + 1];
        acc += dot8(a, x0, x1);
        acc += dot8(b, h0, h1);
    }
    float s = warp_reduce_sum(acc);
    if (lane == 0) g_gates[row] = s + bih[row] + bhh[row];

    // -------- tail-block detection (threadFenceReduction pattern) --------
    __shared__ int s_last;
    __syncthreads();
    if (threadIdx.x == 0) {
        __threadfence();
        unsigned t = atomicAdd(&g_ctr_gates, 1u);
        s_last = (t == GATES_GRID - 1) ? 1 : 0;
        if (s_last) g_ctr_gates = 0;       // reset for next step / next replay
    }
    __syncthreads();
    if (!s_last) return;
    __threadfence();

    // -------- fused LSTM cell update (torch gate order i, f, g, o) --------
    for (int j = threadIdx.x; j < H; j += GATES_BLOCK) {
        float ig = g_gates[j];
        float fg = g_gates[H + j];
        float gg = g_gates[2 * H + j];
        float og = g_gates[3 * H + j];
        float c = sigmoidf_(fg) * g_c[j] + sigmoidf_(ig) * tanhf(gg);
        g_c[j] = c;
        g_h[j] = sigmoidf_(og) * tanhf(c);
    }
}

// ---------------------------------------------------------------------------
// logits: one warp per row (8 rows per block). The last-finishing block
// additionally performs the greedy argmax -> g_tok (fused, saves a launch).
// First-max (lowest index) wins, matching jnp.argmax.
// ---------------------------------------------------------------------------
__global__ void __launch_bounds__(LOGIT_BLOCK)
logits_kernel(const float* __restrict__ bout,
              float* __restrict__ out) {
    int w    = threadIdx.x >> 5;
    int lane = threadIdx.x & 31;
    int row  = blockIdx.x * 8 + w;

    const float4* hh = (const float4*)g_h;
    const uint4*  wt = (const uint4*)(g_Wout + (size_t)row * H);

    float acc = 0.0f;
    #pragma unroll 4
    for (int i = 0; i < H / 8 / 32; i++) {   // 16 iterations per lane
        int c = lane + i * 32;
        uint4  a  = wt[c];
        float4 h0 = hh[2 * c], h1 = hh[2 * c + 1];
        acc += dot8(a, h0, h1);
    }
    float s = warp_reduce_sum(acc);
    if (lane == 0) out[row] = s + bout[row];

    // -------- tail-block detection --------
    __shared__ int s_last;
    __syncthreads();
    if (threadIdx.x == 0) {
        __threadfence();
        unsigned t = atomicAdd(&g_ctr_logits, 1u);
        s_last = (t == LOGIT_GRID - 1) ? 1 : 0;
        if (s_last) g_ctr_logits = 0;
    }
    __syncthreads();
    if (!s_last) return;
    __threadfence();

    // -------- fused argmax over V logits --------
    __shared__ float sv[8];
    __shared__ int   si[8];
    float best = -FLT_MAX;
    int   bi   = 0x7fffffff;
    for (int i = threadIdx.x; i < V; i += LOGIT_BLOCK) {
        float v = out[i];
        if (v > best) { best = v; bi = i; }   // strict > keeps earliest index
    }
    #pragma unroll
    for (int o = 16; o > 0; o >>= 1) {
        float ov = __shfl_down_sync(0xffffffffu, best, o);
        int   oi = __shfl_down_sync(0xffffffffu, bi, o);
        if (ov > best || (ov == best && oi < bi)) { best = ov; bi = oi; }
    }
    if (lane == 0) { sv[w] = best; si[w] = bi; }
    __syncthreads();
    if (w == 0) {
        best = (lane < 8) ? sv[lane] : -FLT_MAX;
        bi   = (lane < 8) ? si[lane] : 0x7fffffff;
        #pragma unroll
        for (int o = 4; o > 0; o >>= 1) {
            float ov = __shfl_down_sync(0xffffffffu, best, o);
            int   oi = __shfl_down_sync(0xffffffffu, bi, o);
            if (ov > best || (ov == best && oi < bi)) { best = ov; bi = oi; }
        }
        if (lane == 0) g_tok = bi;
    }
}

// ---------------------------------------------------------------------------
// kernel_launch: 3 convert + 1 init + 20 x (gates, logits) = 44 launches.
// All plain launches on the capture stream (graph-capturable, allocation-free).
// ---------------------------------------------------------------------------
extern "C" void kernel_launch(void* const* d_in, const int* in_sizes, int n_in,
                              void* d_out, int out_size) {
    const float* imgf  = (const float*)d_in[0];  // image_features [1,1,4096]
    const float* noise = (const float*)d_in[1];  // noise          [1,1,4096]
    const float* emb   = (const float*)d_in[2];  // embedding      [32000,4096]
    const float* Wih   = (const float*)d_in[3];  // W_ih           [16384,4096]
    const float* Whh   = (const float*)d_in[4];  // W_hh           [16384,4096]
    const float* bih   = (const float*)d_in[5];  // b_ih           [16384]
    const float* bhh   = (const float*)d_in[6];  // b_hh           [16384]
    const float* Wout  = (const float*)d_in[7];  // W_out          [32000,4096]
    const float* bout  = (const float*)d_in[8];  // b_out          [32000]
    float* out = (float*)d_out;                  // [20, 32000] fp32 logits

    const int nW8  = G * H / 8;   // 8,388,608  (multiple of 256)
    const int nWo8 = V * H / 8;   // 16,384,000 (multiple of 256)
    convert_wih<<<nW8 / 256, 256>>>((const float4*)Wih);
    convert_whh<<<nW8 / 256, 256>>>((const float4*)Whh);
    convert_wout<<<nWo8 / 256, 256>>>((const float4*)Wout);

    init_kernel<<<(H + 255) / 256, 256>>>(imgf, noise);
    for (int s = 0; s < STEPS; s++) {
        gates_kernel<<<GATES_GRID, GATES_BLOCK>>>(emb, bih, bhh);
        logits_kernel<<<LOGIT_GRID, LOGIT_BLOCK>>>(bout, out + (size_t)s * V);
    }
}

// round 16
// speedup vs baseline: 1.2714x; 1.2714x over previous
#include <cuda_runtime.h>
#include <cuda_fp16.h>
#include <float.h>
#include <math.h>

#define H 4096
#define V 32000
#define G (4 * H)
#define STEPS 20

// Sequential decode state in device globals (no allocation allowed).
__device__ float g_h[H];
__device__ float g_c[H];
__device__ float g_gates[G];
// Packed argmax accumulator: high 32 = monotone float key, low 32 = ~index.
// atomicMax over this is order-independent and reproduces jnp.argmax
// (max value, lowest index on ties).
__device__ unsigned long long g_best;

// fp16 weight cache (static device scratch: 128 + 128 + 250 MB).
__device__ __half g_Wih[(size_t)G * H];
__device__ __half g_Whh[(size_t)G * H];
__device__ __half g_Wout[(size_t)V * H];

// ---------------------------------------------------------------------------
// fp32 -> fp16 conversion: 8 floats (2x float4) -> 1 uint4 per thread.
// Single merged kernel over all three matrices (fewer launches, one ramp).
// ---------------------------------------------------------------------------
__device__ __forceinline__ uint4 f8_to_h8(float4 a, float4 b) {
    __half2 h0 = __floats2half2_rn(a.x, a.y);
    __half2 h1 = __floats2half2_rn(a.z, a.w);
    __half2 h2 = __floats2half2_rn(b.x, b.y);
    __half2 h3 = __floats2half2_rn(b.z, b.w);
    uint4 o;
    o.x = *reinterpret_cast<unsigned*>(&h0);
    o.y = *reinterpret_cast<unsigned*>(&h1);
    o.z = *reinterpret_cast<unsigned*>(&h2);
    o.w = *reinterpret_cast<unsigned*>(&h3);
    return o;
}

#define N_A (G * H / 8)   // 8,388,608 uint4 outputs per gate matrix
#define N_O (V * H / 8)   // 16,384,000 uint4 outputs for W_out

__global__ void convert_all(const float4* __restrict__ Wih,
                            const float4* __restrict__ Whh,
                            const float4* __restrict__ Wout) {
    int i = blockIdx.x * blockDim.x + threadIdx.x;   // < 33,161,216 (fits int)
    if (i < N_A) {
        ((uint4*)g_Wih)[i] = f8_to_h8(Wih[2 * i], Wih[2 * i + 1]);
    } else if (i < 2 * N_A) {
        int j = i - N_A;
        ((uint4*)g_Whh)[j] = f8_to_h8(Whh[2 * j], Whh[2 * j + 1]);
    } else {
        int j = i - 2 * N_A;
        ((uint4*)g_Wout)[j] = f8_to_h8(Wout[2 * j], Wout[2 * j + 1]);
    }
}

// ---------------------------------------------------------------------------
// init: h0 = noise + image_features, c0 = 0, g_best encodes tok0 = 0.
// ---------------------------------------------------------------------------
__global__ void init_kernel(const float* __restrict__ imgf,
                            const float* __restrict__ noise) {
    int i = blockIdx.x * blockDim.x + threadIdx.x;
    if (i < H) {
        g_h[i] = imgf[i] + noise[i];
        g_c[i] = 0.0f;
    }
    // low 32 bits = ~0 -> tok = ~0xFFFFFFFF = 0 (START_TOKEN)
    if (i == 0) g_best = 0xFFFFFFFFull;
}

// ---------------------------------------------------------------------------
// block-wide sum reduce, 128 threads (4 warps). Result valid in thread 0.
// ---------------------------------------------------------------------------
__device__ __forceinline__ float block_reduce_sum_128(float v) {
    __shared__ float s[4];
    int lane = threadIdx.x & 31;
    int w    = threadIdx.x >> 5;
    #pragma unroll
    for (int o = 16; o > 0; o >>= 1)
        v += __shfl_down_sync(0xffffffffu, v, o);
    if (lane == 0) s[w] = v;
    __syncthreads();
    if (w == 0) {
        v = (lane < 4) ? s[lane] : 0.0f;
        #pragma unroll
        for (int o = 2; o > 0; o >>= 1)
            v += __shfl_down_sync(0xffffffffu, v, o);
    }
    return v;
}

// 8 fp16 weights (one uint4) dotted with 8 fp32 activations, fp32 accumulate.
__device__ __forceinline__ float dot8(uint4 a, float4 v0, float4 v1) {
    const __half2* p = reinterpret_cast<const __half2*>(&a);
    float2 f0 = __half22float2(p[0]);
    float2 f1 = __half22float2(p[1]);
    float2 f2 = __half22float2(p[2]);
    float2 f3 = __half22float2(p[3]);
    return f0.x * v0.x + f0.y * v0.y + f1.x * v0.z + f1.y * v0.w
         + f2.x * v1.x + f2.y * v1.y + f3.x * v1.z + f3.y * v1.w;
}

// Monotone float -> uint key; pack with ~idx so atomicMax == first-argmax.
__device__ __forceinline__ unsigned long long pack_max(float v, int idx) {
    unsigned b = __float_as_uint(v);
    b = (b & 0x80000000u) ? ~b : (b | 0x80000000u);
    return ((unsigned long long)b << 32) | (unsigned)(~idx);
}

// ---------------------------------------------------------------------------
// gates[row] = Wih_h[row,:] . emb[tok] + b_ih[row] + Whh_h[row,:] . h + b_hh[row]
// One block per row (16384 blocks x 128 threads) — exact R6 structure.
// tok is unpacked from g_best (filled by previous step's logits kernel).
// ---------------------------------------------------------------------------
__global__ void __launch_bounds__(128)
gates_kernel(const float* __restrict__ emb,
             const float* __restrict__ bih,
             const float* __restrict__ bhh) {
    int row = blockIdx.x;
    int t   = threadIdx.x;

    int tok = (int)(~(unsigned)g_best);   // low 32 bits hold ~argmax_index

    const float4* x  = (const float4*)(emb + (size_t)tok * H);
    const float4* hh = (const float4*)g_h;
    const uint4*  wi = (const uint4*)(g_Wih + (size_t)row * H);
    const uint4*  wh = (const uint4*)(g_Whh + (size_t)row * H);

    float acc = 0.0f;
    #pragma unroll
    for (int i = 0; i < H / 8 / 128; i++) {   // 4 iterations, 8 elems each
        int c = t + i * 128;
        uint4  a  = wi[c];
        uint4  b  = wh[c];
        float4 x0 = x[2 * c], x1 = x[2 * c + 1];
        float4 h0 = hh[2 * c], h1 = hh[2 * c + 1];
        acc += dot8(a, x0, x1);
        acc += dot8(b, h0, h1);
    }
    float s = block_reduce_sum_128(acc);
    if (t == 0) g_gates[row] = s + bih[row] + bhh[row];
}

// ---------------------------------------------------------------------------
// LSTM cell update (torch gate order i, f, g, o). Also resets the argmax
// accumulator for this step's logits kernel (runs between gates and logits).
// ---------------------------------------------------------------------------
__device__ __forceinline__ float sigmoidf_(float x) {
    return 1.0f / (1.0f + expf(-x));
}

__global__ void cell_kernel() {
    int j = blockIdx.x * blockDim.x + threadIdx.x;
    if (j == 0) g_best = 0ull;   // identity for atomicMax; tok already consumed
    if (j >= H) return;
    float ig = g_gates[j];
    float fg = g_gates[H + j];
    float gg = g_gates[2 * H + j];
    float og = g_gates[3 * H + j];
    float c = sigmoidf_(fg) * g_c[j] + sigmoidf_(ig) * tanhf(gg);
    g_c[j] = c;
    g_h[j] = sigmoidf_(og) * tanhf(c);
}

// ---------------------------------------------------------------------------
// logits[row] = Wout_h[row,:] . h + b_out[row]  (32000 blocks x 128 threads)
// plus fused argmax contribution: one atomicMax per block (order-independent).
// ---------------------------------------------------------------------------
__global__ void __launch_bounds__(128)
logits_kernel(const float* __restrict__ bout,
              float* __restrict__ out) {
    int row = blockIdx.x;
    int t   = threadIdx.x;

    const float4* hh = (const float4*)g_h;
    const uint4*  w  = (const uint4*)(g_Wout + (size_t)row * H);

    float acc = 0.0f;
    #pragma unroll
    for (int i = 0; i < H / 8 / 128; i++) {   // 4 iterations
        int c = t + i * 128;
        uint4  a  = w[c];
        float4 h0 = hh[2 * c], h1 = hh[2 * c + 1];
        acc += dot8(a, h0, h1);
    }
    float s = block_reduce_sum_128(acc);
    if (t == 0) {
        float logit = s + bout[row];
        out[row] = logit;
        atomicMax(&g_best, pack_max(logit, row));
    }
}

// ---------------------------------------------------------------------------
// kernel_launch: 1 convert + 1 init + 20 x (gates, cell, logits) = 42 launches.
// All plain launches on the capture stream (graph-capturable, allocation-free).
// ---------------------------------------------------------------------------
extern "C" void kernel_launch(void* const* d_in, const int* in_sizes, int n_in,
                              void* d_out, int out_size) {
    const float* imgf  = (const float*)d_in[0];  // image_features [1,1,4096]
    const float* noise = (const float*)d_in[1];  // noise          [1,1,4096]
    const float* emb   = (const float*)d_in[2];  // embedding      [32000,4096]
    const float* Wih   = (const float*)d_in[3];  // W_ih           [16384,4096]
    const float* Whh   = (const float*)d_in[4];  // W_hh           [16384,4096]
    const float* bih   = (const float*)d_in[5];  // b_ih           [16384]
    const float* bhh   = (const float*)d_in[6];  // b_hh           [16384]
    const float* Wout  = (const float*)d_in[7];  // W_out          [32000,4096]
    const float* bout  = (const float*)d_in[8];  // b_out          [32000]
    float* out = (float*)d_out;                  // [20, 32000] fp32 logits

    const int nConv = 2 * N_A + N_O;   // 33,161,216 (multiple of 256)
    convert_all<<<nConv / 256, 256>>>((const float4*)Wih, (const float4*)Whh,
                                      (const float4*)Wout);

    init_kernel<<<(H + 255) / 256, 256>>>(imgf, noise);
    for (int s = 0; s < STEPS; s++) {
        gates_kernel<<<G, 128>>>(emb, bih, bhh);
        cell_kernel<<<H / 256, 256>>>();
        logits_kernel<<<V, 128>>>(bout, out + (size_t)s * V);
    }
}